// round 3
// baseline (speedup 1.0000x reference)
#include <cuda_runtime.h>

// ---------------------------------------------------------------------------
// MaskRemoval — R3
//   k_sort    : stable descending rank sort (1 CTA)
//   k_bits    : PARALLEL per-ROI mask rasterization -> bit words in global
//               scratch + msum, via warp-ballot (one warp per 32px word);
//               also zeroes the class bitmasks
//   k_scan    : one CTA/class; sequential suppression is now MEMORY-ONLY
//               (popc(bits & cmask), OR-merge)
//   k_compact : prefix scan -> slot table + keep_inds
//   k_zero    : 256MB streaming zero, run on a SIDE STREAM overlapped with
//               the sort/bits/scan/compact chain (fork-join via events)
//   k_paste   : one CTA per slot, bilinear values inside kept boxes
// ---------------------------------------------------------------------------

#define MAXN   128
#define NCLS   80
#define MM     28
#define IMG_H  800
#define IMG_W  800
#define WPR    ((IMG_W + 31) / 32)     // 25 words per image row
#define BOXMAX 384                     // max clipped box extent precomputed
#define BITSW  8192                    // words of bit-scratch per ROI

__device__ int g_order[MAXN];
__device__ int g_bx0[MAXN], g_by0[MAXN];
__device__ int g_bx1[MAXN], g_by1[MAXN];
__device__ int g_cls[MAXN];
__device__ int g_keep[MAXN];
__device__ int g_slot[MAXN];
__device__ int g_msum[MAXN];
__device__ unsigned int g_bits[MAXN][BITSW];          // 4 MB ROI bit rasters
__device__ unsigned int g_cmask[NCLS][IMG_H * WPR];   // 6.4 MB class bitmasks

// ---------------------------------------------------------------------------
__global__ __launch_bounds__(128) void k_sort(const float* __restrict__ rois,
                                              const float* __restrict__ prob,
                                              const int*   __restrict__ clsidx,
                                              int N) {
    int i = threadIdx.x;
    if (i < N) {
        float pi = prob[i];
        int r = 0;
        for (int j = 0; j < N; j++) {
            float pj = prob[j];
            r += (pj > pi) || (pj == pi && j < i);    // stable descending rank
        }
        g_order[r] = i;
        g_keep[i] = 0;
    }
    __syncthreads();
    if (i < N) {
        int o = g_order[i];
        g_bx0[i] = (int)rois[4 * o + 0];   // trunc-toward-zero == astype(int32)
        g_by0[i] = (int)rois[4 * o + 1];
        g_bx1[i] = (int)rois[4 * o + 2];
        g_by1[i] = (int)rois[4 * o + 3];
        g_cls[i] = clsidx[o] - 1;
    }
}

// exact reference bilinear form (keep decision thresholds on val>0)
__device__ __forceinline__ float bilin_ref(const float* lg, float sx, float sy) {
    int ix0 = (int)sx;
    int iy0 = (int)sy;
    int ix1 = min(ix0 + 1, MM - 1);
    int iy1 = min(iy0 + 1, MM - 1);
    float fx = sx - (float)ix0;
    float fy = sy - (float)iy0;
    float v00 = lg[iy0 * MM + ix0], v01 = lg[iy0 * MM + ix1];
    float v10 = lg[iy1 * MM + ix0], v11 = lg[iy1 * MM + ix1];
    return (1.0f - fy) * ((1.0f - fx) * v00 + fx * v01)
         +         fy  * ((1.0f - fx) * v10 + fx * v11);
}

// ---------------------------------------------------------------------------
// Parallel rasterization: one CTA per sorted ROI, one warp per 32-pixel word.
__global__ __launch_bounds__(256) void k_bits(const float* __restrict__ mask_prob,
                                              int N) {
    int i = blockIdx.x;

    // cooperative zero of class bitmasks (split across the N CTAs)
    {
        long long tot = (long long)NCLS * IMG_H * WPR;
        long long per = (tot + gridDim.x - 1) / gridDim.x;
        long long lo = (long long)i * per;
        long long hi = min(lo + per, tot);
        unsigned int* cmf = &g_cmask[0][0];
        for (long long w = lo + threadIdx.x; w < hi; w += blockDim.x) cmf[w] = 0u;
    }
    if (i >= N) return;

    __shared__ float lg[MM * MM];
    __shared__ int   s_ix0[BOXMAX], s_ix1[BOXMAX];
    __shared__ float s_fx[BOXMAX];
    __shared__ int   s_iy0[BOXMAX], s_iy1[BOXMAX];
    __shared__ float s_fy[BOXMAX];
    __shared__ int   s_cnt;

    int x0 = g_bx0[i], y0 = g_by0[i], x1 = g_bx1[i], y1 = g_by1[i];
    int xs0 = max(x0, 0), xs1 = min(x1 + 1, IMG_W);
    int ys0 = max(y0, 0), ys1 = min(y1 + 1, IMG_H);
    int bw = xs1 - xs0, bh = ys1 - ys0;

    if (threadIdx.x == 0) { s_cnt = 0; g_msum[i] = 0; }

    if (bw <= 0 || bh <= 0) return;

    int o = g_order[i];
    const float* lp = mask_prob + (long long)o * (MM * MM);
    for (int t = threadIdx.x; t < MM * MM; t += blockDim.x) lg[t] = lp[t];

    float wv = fmaxf((float)(x1 - x0 + 1), 1.0f);
    float hv = fmaxf((float)(y1 - y0 + 1), 1.0f);
    float scx = 28.0f / wv, scy = 28.0f / hv;

    bool pre = (bw <= BOXMAX) && (bh <= BOXMAX);
    if (pre) {
        for (int t = threadIdx.x; t < bw; t += blockDim.x) {
            float sx = fminf(fmaxf(((float)(xs0 + t) - (float)x0 + 0.5f) * scx - 0.5f, 0.0f), 27.0f);
            int ix0 = (int)sx;
            s_ix0[t] = ix0;
            s_ix1[t] = min(ix0 + 1, MM - 1);
            s_fx[t]  = sx - (float)ix0;
        }
        for (int t = threadIdx.x; t < bh; t += blockDim.x) {
            float sy = fminf(fmaxf(((float)(ys0 + t) - (float)y0 + 0.5f) * scy - 0.5f, 0.0f), 27.0f);
            int iy0 = (int)sy;
            s_iy0[t] = iy0;
            s_iy1[t] = min(iy0 + 1, MM - 1);
            s_fy[t]  = sy - (float)iy0;
        }
    }
    __syncthreads();

    int xw0 = xs0 >> 5, xw1 = (xs1 + 31) >> 5;
    int nwx = xw1 - xw0;
    int total = nwx * bh;
    bool fits = (total <= BITSW);

    int warp = threadIdx.x >> 5;
    int lane = threadIdx.x & 31;
    int nwarps = blockDim.x >> 5;
    int lm = 0;

    for (int k = warp; k < total; k += nwarps) {
        int ry = k / nwx;
        int xw = xw0 + (k - ry * nwx);
        int x  = (xw << 5) + lane;
        bool on = false;
        if (x >= xs0 && x < xs1) {
            float val;
            if (pre) {
                int col = x - xs0;
                int iy0 = s_iy0[ry], iy1 = s_iy1[ry];
                float fy = s_fy[ry];
                int ix0 = s_ix0[col], ix1 = s_ix1[col];
                float fx = s_fx[col];
                const float* r0 = lg + iy0 * MM;
                const float* r1 = lg + iy1 * MM;
                val = (1.0f - fy) * ((1.0f - fx) * r0[ix0] + fx * r0[ix1])
                    +         fy  * ((1.0f - fx) * r1[ix0] + fx * r1[ix1]);
            } else {
                int y = ys0 + ry;
                float sy = fminf(fmaxf(((float)y - (float)y0 + 0.5f) * scy - 0.5f, 0.0f), 27.0f);
                float sx = fminf(fmaxf(((float)x - (float)x0 + 0.5f) * scx - 0.5f, 0.0f), 27.0f);
                val = bilin_ref(lg, sx, sy);
            }
            on = (val > 0.0f);
        }
        unsigned int bits = __ballot_sync(0xffffffffu, on);
        if (lane == 0) {
            if (fits) g_bits[i][k] = bits;
            lm += __popc(bits);
        }
    }
    // reduce msum (lane0 of each warp holds partials)
    if (lane == 0 && lm) atomicAdd(&s_cnt, lm);
    __syncthreads();
    if (threadIdx.x == 0) g_msum[i] = s_cnt;
}

// ---------------------------------------------------------------------------
// Sequential suppression per class — memory-only when bits fit.
__global__ __launch_bounds__(256) void k_scan(const float* __restrict__ mask_prob,
                                              int N) {
    int c = blockIdx.x;
    unsigned int* cm = g_cmask[c];
    __shared__ int s_ovl, s_keep;
    __shared__ float lg[MM * MM];

    for (int i = 0; i < N; i++) {
        if (g_cls[i] != c) continue;                  // uniform per-CTA branch

        int x0 = g_bx0[i], y0 = g_by0[i], x1 = g_bx1[i], y1 = g_by1[i];
        int xs0 = max(x0, 0), xs1 = min(x1 + 1, IMG_W);
        int ys0 = max(y0, 0), ys1 = min(y1 + 1, IMG_H);
        int bw = xs1 - xs0, bh = ys1 - ys0;
        int msum = g_msum[i];

        if (bw <= 0 || bh <= 0 || msum == 0) {
            if (threadIdx.x == 0) g_keep[i] = 0;
            continue;
        }

        int xw0 = xs0 >> 5, xw1 = (xs1 + 31) >> 5;
        int nwx = xw1 - xw0;
        int total = nwx * bh;
        bool fits = (total <= BITSW);

        if (threadIdx.x == 0) s_ovl = 0;
        __syncthreads();

        int lo = 0;
        if (fits) {
            const unsigned int* bi = g_bits[i];
            for (int k = threadIdx.x; k < total; k += blockDim.x) {
                unsigned int b = bi[k];
                if (b) {
                    int ry = k / nwx;
                    int y  = ys0 + ry;
                    int xw = xw0 + (k - ry * nwx);
                    lo += __popc(b & cm[y * WPR + xw]);
                }
            }
        } else {
            // rare fallback: recompute bits on the fly
            int o = g_order[i];
            const float* lp = mask_prob + (long long)o * (MM * MM);
            for (int t = threadIdx.x; t < MM * MM; t += blockDim.x) lg[t] = lp[t];
            __syncthreads();
            float wv = fmaxf((float)(x1 - x0 + 1), 1.0f);
            float hv = fmaxf((float)(y1 - y0 + 1), 1.0f);
            float scx = 28.0f / wv, scy = 28.0f / hv;
            for (int k = threadIdx.x; k < total; k += blockDim.x) {
                int ry = k / nwx;
                int y  = ys0 + ry;
                int xw = xw0 + (k - ry * nwx);
                unsigned int cw = cm[y * WPR + xw];
                if (!cw) continue;
                float sy = fminf(fmaxf(((float)y - (float)y0 + 0.5f) * scy - 0.5f, 0.0f), 27.0f);
                int xlo2 = max(xs0, xw << 5);
                int xhi2 = min(xs1, (xw << 5) + 32);
                for (int x = xlo2; x < xhi2; x++) {
                    if (cw & (1u << (x & 31))) {
                        float sx = fminf(fmaxf(((float)x - (float)x0 + 0.5f) * scx - 0.5f, 0.0f), 27.0f);
                        if (bilin_ref(lg, sx, sy) > 0.0f) lo++;
                    }
                }
            }
        }
        #pragma unroll
        for (int off = 16; off > 0; off >>= 1)
            lo += __shfl_down_sync(0xffffffffu, lo, off);
        if ((threadIdx.x & 31) == 0 && lo) atomicAdd(&s_ovl, lo);
        __syncthreads();

        if (threadIdx.x == 0) {
            int kp = ((float)s_ovl <= 0.3f * (float)msum);
            s_keep = kp;
            g_keep[i] = kp;
        }
        __syncthreads();

        if (s_keep) {
            if (fits) {
                const unsigned int* bi = g_bits[i];
                for (int k = threadIdx.x; k < total; k += blockDim.x) {
                    unsigned int b = bi[k];
                    if (b) {
                        int ry = k / nwx;
                        int y  = ys0 + ry;
                        int xw = xw0 + (k - ry * nwx);
                        cm[y * WPR + xw] |= b;
                    }
                }
            } else {
                float wv = fmaxf((float)(x1 - x0 + 1), 1.0f);
                float hv = fmaxf((float)(y1 - y0 + 1), 1.0f);
                float scx = 28.0f / wv, scy = 28.0f / hv;
                for (int k = threadIdx.x; k < total; k += blockDim.x) {
                    int ry = k / nwx;
                    int y  = ys0 + ry;
                    int xw = xw0 + (k - ry * nwx);
                    float sy = fminf(fmaxf(((float)y - (float)y0 + 0.5f) * scy - 0.5f, 0.0f), 27.0f);
                    int xlo2 = max(xs0, xw << 5);
                    int xhi2 = min(xs1, (xw << 5) + 32);
                    unsigned int bits = 0u;
                    for (int x = xlo2; x < xhi2; x++) {
                        float sx = fminf(fmaxf(((float)x - (float)x0 + 0.5f) * scx - 0.5f, 0.0f), 27.0f);
                        if (bilin_ref(lg, sx, sy) > 0.0f) bits |= (1u << (x & 31));
                    }
                    if (bits) cm[y * WPR + xw] |= bits;
                }
            }
        }
        __syncthreads();
    }
}

// ---------------------------------------------------------------------------
__global__ __launch_bounds__(128) void k_compact(float* __restrict__ out_keep,
                                                 int N, int has_keep) {
    __shared__ int pf[128];
    int i = threadIdx.x;
    int k = (i < N) ? g_keep[i] : 0;
    pf[i] = k;
    __syncthreads();
    #pragma unroll
    for (int off = 1; off < 128; off <<= 1) {
        int v = (i >= off) ? pf[i - off] : 0;
        __syncthreads();
        pf[i] += v;
        __syncthreads();
    }
    if (i < N) g_slot[i] = -1;
    __syncthreads();
    if (i < N && k) g_slot[pf[i] - 1] = i;
    __syncthreads();
    if (has_keep && i < N) {
        int s = g_slot[i];
        out_keep[i] = (s >= 0) ? (float)g_order[s] : -1.0f;
    }
}

// ---------------------------------------------------------------------------
__global__ __launch_bounds__(256) void k_zero(float4* __restrict__ p, long long n4) {
    long long i = (long long)blockIdx.x * blockDim.x + threadIdx.x;
    long long stride = (long long)gridDim.x * blockDim.x;
    float4 z = make_float4(0.f, 0.f, 0.f, 0.f);
    for (; i < n4; i += stride) p[i] = z;
}

// ---------------------------------------------------------------------------
__global__ __launch_bounds__(256) void k_paste(const float* __restrict__ mask_prob,
                                               float* __restrict__ energy) {
    int slot = blockIdx.x;
    int s = g_slot[slot];
    if (s < 0) return;

    __shared__ float lg[MM * MM];
    int o = g_order[s];
    const float* lp = mask_prob + (long long)o * (MM * MM);
    for (int t = threadIdx.x; t < MM * MM; t += blockDim.x) lg[t] = lp[t];
    __syncthreads();

    int x0 = g_bx0[s], y0 = g_by0[s], x1 = g_bx1[s], y1 = g_by1[s];
    int xs0 = max(x0, 0), xs1 = min(x1 + 1, IMG_W);
    int ys0 = max(y0, 0), ys1 = min(y1 + 1, IMG_H);
    int bw = xs1 - xs0, bh = ys1 - ys0;
    if (bw <= 0 || bh <= 0) return;

    float wv = fmaxf((float)(x1 - x0 + 1), 1.0f);
    float hv = fmaxf((float)(y1 - y0 + 1), 1.0f);
    float scx = 28.0f / wv, scy = 28.0f / hv;

    float* base = energy + (long long)slot * IMG_H * IMG_W;
    int total = bw * bh;
    for (int k = threadIdx.x; k < total; k += blockDim.x) {
        int ry = k / bw;
        int rx = k - ry * bw;
        int y = ys0 + ry, x = xs0 + rx;
        float sy = fminf(fmaxf(((float)y - (float)y0 + 0.5f) * scy - 0.5f, 0.0f), 27.0f);
        float sx = fminf(fmaxf(((float)x - (float)x0 + 0.5f) * scx - 0.5f, 0.0f), 27.0f);
        base[y * IMG_W + x] = bilin_ref(lg, sx, sy);
    }
}

// ---------------------------------------------------------------------------
extern "C" void kernel_launch(void* const* d_in, const int* in_sizes, int n_in,
                              void* d_out, int out_size) {
    const float* rois  = (const float*)d_in[0];
    const float* prob  = (const float*)d_in[1];
    const float* mp    = (const float*)d_in[2];
    const int*   cidx  = (const int*)d_in[3];

    int N = in_sizes[1];
    if (N > MAXN) N = MAXN;

    float* out = (float*)d_out;
    long long HW = (long long)IMG_H * IMG_W;
    int has_keep = ((long long)out_size == (long long)N + (long long)N * HW) ? 1 : 0;
    float* energy = out + (has_keep ? N : 0);
    long long n4 = ((long long)N * HW) / 4;

    // side stream + events: created once; host code only runs during
    // capture/correctness, graph replay keeps the fork-join structure.
    static cudaStream_t s_side = nullptr;
    static cudaEvent_t ev_fork = nullptr, ev_join = nullptr;
    if (!s_side) {
        cudaStreamCreateWithFlags(&s_side, cudaStreamNonBlocking);
        cudaEventCreateWithFlags(&ev_fork, cudaEventDisableTiming);
        cudaEventCreateWithFlags(&ev_join, cudaEventDisableTiming);
    }

    // fork: k_zero streams 256MB on the side while the decision chain runs
    cudaEventRecord(ev_fork, 0);
    cudaStreamWaitEvent(s_side, ev_fork, 0);
    k_zero<<<2048, 256, 0, s_side>>>((float4*)energy, n4);
    cudaEventRecord(ev_join, s_side);

    k_sort<<<1, 128>>>(rois, prob, cidx, N);
    k_bits<<<N, 256>>>(mp, N);
    k_scan<<<NCLS, 256>>>(mp, N);
    k_compact<<<1, 128>>>(out, N, has_keep);

    // join: paste needs both the zeroed tensor and the slot table
    cudaStreamWaitEvent(0, ev_join, 0);
    k_paste<<<N, 256>>>(mp, energy);
}